// round 4
// baseline (speedup 1.0000x reference)
#include <cuda_runtime.h>
#include <math.h>

#define BB 2
#define LL 1024
#define DD 1024
#define NN 16
#define RR 64

// scratch (no device allocations allowed)
__device__ float g_tmp[BB * LL * RR];
__device__ float g_delta[BB * LL * DD];
__device__ float g_Bt[BB * LL * NN];
__device__ float g_Ct[BB * LL * NN];

// ---------------- skinny GEMM: C[M,N] = A[M,K] @ W[K,N] ----------------
// Thread-per-output, strictly sequential k-ascending fmaf chain (bit-exact).
template <int N_, int TM, int CK>
__global__ void __launch_bounds__(256) skinny_gemm(
    const float* __restrict__ A, const float* __restrict__ W,
    float* __restrict__ C, int M, int K)
{
    __shared__ float As[TM][CK];
    __shared__ float Ws[CK][N_];
    int tid = threadIdx.x;
    int m0 = blockIdx.x * TM;
    int r = tid / N_;
    int n = tid % N_;
    float acc = 0.f;

    for (int k0 = 0; k0 < K; k0 += CK) {
        __syncthreads();
        for (int i = tid; i < TM * CK; i += 256) {
            int rr = i / CK, kk = i % CK;
            As[rr][kk] = A[(size_t)(m0 + rr) * K + (k0 + kk)];
        }
        for (int i = tid; i < CK * N_; i += 256) {
            int kk = i / N_, nn = i % N_;
            Ws[kk][nn] = W[(size_t)(k0 + kk) * N_ + nn];
        }
        __syncthreads();
#pragma unroll
        for (int k = 0; k < CK; ++k)
            acc = fmaf(As[r][k], Ws[k][n], acc);
    }
    C[(size_t)(m0 + r) * N_ + n] = acc;
}

// ---------------- fused Bt/Ct GEMM ----------------
// Both outputs share the A staging; each acc is the same k-ascending fmaf
// chain as before => bit-identical results, one launch instead of two.
__global__ void __launch_bounds__(256) btct_gemm(
    const float* __restrict__ A, const float* __restrict__ WB,
    const float* __restrict__ WC, float* __restrict__ Bt,
    float* __restrict__ Ct, int K)
{
    __shared__ float As[16][64];
    __shared__ float WBs[64][16];
    __shared__ float WCs[64][16];
    int tid = threadIdx.x;
    int m0 = blockIdx.x * 16;
    int r = tid >> 4;
    int n = tid & 15;
    float accB = 0.f, accC = 0.f;

    for (int k0 = 0; k0 < K; k0 += 64) {
        __syncthreads();
        for (int i = tid; i < 16 * 64; i += 256) {
            int rr = i >> 6, kk = i & 63;
            As[rr][kk] = A[(size_t)(m0 + rr) * K + (k0 + kk)];
        }
        for (int i = tid; i < 64 * 16; i += 256) {
            int kk = i >> 4, nn = i & 15;
            WBs[kk][nn] = WB[(size_t)(k0 + kk) * 16 + nn];
            WCs[kk][nn] = WC[(size_t)(k0 + kk) * 16 + nn];
        }
        __syncthreads();
#pragma unroll
        for (int k = 0; k < 64; ++k) {
            float a = As[r][k];
            accB = fmaf(a, WBs[k][n], accB);
            accC = fmaf(a, WCs[k][n], accC);
        }
    }
    Bt[(size_t)(m0 + r) * 16 + n] = accB;
    Ct[(size_t)(m0 + r) * 16 + n] = accC;
}

// ---------------- delta GEMM + softplus (unchanged numerics) ----------------
__global__ void __launch_bounds__(256) delta_gemm(
    const float* __restrict__ T, const float* __restrict__ W,
    float* __restrict__ C)
{
    __shared__ float ts[8][64];
    int tid = threadIdx.x;
    int m0 = blockIdx.y * 8;
    int n  = blockIdx.x * 256 + tid;

    for (int i = tid; i < 8 * 64; i += 256)
        ts[i / 64][i % 64] = T[(size_t)(m0 + i / 64) * 64 + (i % 64)];
    __syncthreads();

    float acc[8];
#pragma unroll
    for (int r = 0; r < 8; ++r) acc[r] = 0.f;

#pragma unroll
    for (int k = 0; k < 64; ++k) {
        float w = W[(size_t)k * 1024 + n];
#pragma unroll
        for (int r = 0; r < 8; ++r)
            acc[r] = fmaf(ts[r][k], w, acc[r]);
    }

#pragma unroll
    for (int r = 0; r < 8; ++r) {
        float v = acc[r];
        v = fmaxf(v, 0.f) + log1pf(expf(-fabsf(v)));
        C[(size_t)(m0 + r) * 1024 + n] = v;
    }
}

// ---------------- one recurrence step: EXACT op sequence of the R2/R3 scan ----
__device__ __forceinline__ void res_step(
    float& hx, float& hy, float dv, float An,
    float xv, float bn, float sphi, float cphi)
{
    // fractal_compress(h, e)
    float mag = __fsqrt_rn(__fadd_rn(__fadd_rn(__fmul_rn(hx, hx), __fmul_rn(hy, hy)), 1e-8f));
    float ph  = atan2f(hy, __fadd_rn(hx, 1e-10f));
    float e   = __fadd_rn(1.0f, __fmul_rn(dv, An));
    float cm  = fminf(expf(__fmul_rn(e, logf(__fadd_rn(mag, 1e-8f)))), 10.0f);
    float sph, cph;
    sincosf(ph, &sph, &cph);
    float hcx = __fmul_rn(cm, cph);
    float hcy = __fmul_rn(cm, sph);

    // injection on carrier phases
    float u   = __fmul_rn(xv, bn);
    float ijx = __fmul_rn(u, cphi);
    float ijy = __fmul_rn(u, sphi);

    // resonance gate: gamma = 0.5 * cos((pa-pb)/2)^2
    float pa = atan2f(ijy, __fadd_rn(ijx, 1e-10f));
    float pb = atan2f(hcy, __fadd_rn(hcx, 1e-10f));
    float cd = cosf(__fmul_rn(__fsub_rn(pa, pb), 0.5f));
    float gam = __fmul_rn(0.5f, __fmul_rn(cd, cd));

    // inject + mag_squash
    float sx = __fadd_rn(hcx, __fmul_rn(gam, ijx));
    float sy = __fadd_rn(hcy, __fmul_rn(gam, ijy));
    float sm = __fsqrt_rn(__fadd_rn(__fadd_rn(__fmul_rn(sx, sx), __fmul_rn(sy, sy)), 1e-8f));
    float ps = atan2f(sy, __fadd_rn(sx, 1e-10f));
    float th = tanhf(sm);
    float sps, cps;
    sincosf(ps, &sps, &cps);
    hx = __fmul_rn(th, cps);
    hy = __fmul_rn(th, sps);
}

// ---------------- sequential scan: 2 independent chains per thread ----------
// Thread handles (b,d, n=np) and (b,d, n=np+8): two independent dependency
// chains interleave in the pipeline (2x latency hiding); per-chain numerics
// are bit-identical to the passing kernel.
__global__ void __launch_bounds__(128) scan2_k(
    const float* __restrict__ x, const float* __restrict__ A_log,
    const float* __restrict__ Dskip, float* __restrict__ y)
{
    int tid = threadIdx.x;                // 0..127
    int bid = blockIdx.x;                 // 0..127
    int b = bid >> 6;                     // 0..1
    int d = ((bid & 63) << 4) | (tid >> 3);
    int np = tid & 7;                     // chain A: n=np, chain B: n=np+8

    float An0 = expf(A_log[np]);
    float An1 = expf(A_log[np + 8]);
    float phi0 = (float)np * 0.39269908169872414f;
    float phi1 = (float)(np + 8) * 0.39269908169872414f;
    float sphi0, cphi0, sphi1, cphi1;
    sincosf(phi0, &sphi0, &cphi0);
    sincosf(phi1, &sphi1, &cphi1);
    float hx0 = __fmul_rn(0.01f, cphi0), hy0 = __fmul_rn(0.01f, sphi0);
    float hx1 = __fmul_rn(0.01f, cphi1), hy1 = __fmul_rn(0.01f, sphi1);
    float dsk = Dskip[d];

    size_t rowbase = ((size_t)b * LL) * DD + d;
    const float* xp = x + rowbase;
    const float* dp = g_delta + rowbase;
    const float* bp = g_Bt + ((size_t)b * LL) * NN + np;
    const float* cp = g_Ct + ((size_t)b * LL) * NN + np;
    float* yp = y + rowbase;

    float xv  = __ldg(xp);
    float dv  = __ldg(dp);
    float bn0 = __ldg(bp);
    float bn1 = __ldg(bp + 8);
    float cn0 = __ldg(cp);
    float cn1 = __ldg(cp + 8);

#pragma unroll 2
    for (int t = 0; t < LL; ++t) {
        int tn = (t < LL - 1) ? (t + 1) : t;
        float xv2  = __ldg(xp + (size_t)tn * DD);
        float dv2  = __ldg(dp + (size_t)tn * DD);
        float bn0n = __ldg(bp + tn * NN);
        float bn1n = __ldg(bp + tn * NN + 8);
        float cn0n = __ldg(cp + tn * NN);
        float cn1n = __ldg(cp + tn * NN + 8);

        res_step(hx0, hy0, dv, An0, xv, bn0, sphi0, cphi0);
        res_step(hx1, hy1, dv, An1, xv, bn1, sphi1, cphi1);

        // readout: sum over 16 n (pair add + 3-level tree in 8-lane group)
        float v = __fadd_rn(__fmul_rn(hx0, cn0), __fmul_rn(hx1, cn1));
        v += __shfl_xor_sync(0xffffffffu, v, 4);
        v += __shfl_xor_sync(0xffffffffu, v, 2);
        v += __shfl_xor_sync(0xffffffffu, v, 1);
        if (np == 0) yp[(size_t)t * DD] = __fadd_rn(__fmul_rn(xv, dsk), v);

        xv = xv2; dv = dv2; bn0 = bn0n; bn1 = bn1n; cn0 = cn0n; cn1 = cn1n;
    }
}

extern "C" void kernel_launch(void* const* d_in, const int* in_sizes, int n_in,
                              void* d_out, int out_size)
{
    const float *x = 0, *A_log = 0, *W_dt1 = 0, *W_dt2 = 0, *W_B = 0, *W_C = 0, *Dskip = 0;
    for (int i = 0; i < n_in; ++i) {
        const float* p = (const float*)d_in[i];
        int s = in_sizes[i];
        if (s == BB * LL * DD)      { if (!x) x = p; }
        else if (s == NN)           { if (!A_log) A_log = p; }
        else if (s == DD * RR)      { if (!W_dt1) W_dt1 = p; else W_dt2 = p; }
        else if (s == DD * NN)      { if (!W_B) W_B = p; else W_C = p; }
        else if (s == DD)           { if (!Dskip) Dskip = p; }
    }
    float* y = (float*)d_out;

    float *tmp, *delta, *bt, *ct;
    cudaGetSymbolAddress((void**)&tmp,   g_tmp);
    cudaGetSymbolAddress((void**)&delta, g_delta);
    cudaGetSymbolAddress((void**)&bt,    g_Bt);
    cudaGetSymbolAddress((void**)&ct,    g_Ct);

    const int M = BB * LL;  // 2048
    // tmp = x @ W_dt1      (2048 x 64, K=1024)
    skinny_gemm<64, 4, 64><<<M / 4, 256>>>(x, W_dt1, tmp, M, DD);
    // delta = softplus(tmp @ W_dt2)
    delta_gemm<<<dim3(4, M / 8), 256>>>(tmp, W_dt2, delta);
    // Bt = x @ W_B, Ct = x @ W_C (fused, bit-identical chains)
    btct_gemm<<<M / 16, 256>>>(x, W_B, W_C, bt, ct, DD);
    // sequential scan: 2 chains/thread
    scan2_k<<<128, 128>>>(x, A_log, Dskip, y);
}

// round 5
// speedup vs baseline: 1.5734x; 1.5734x over previous
#include <cuda_runtime.h>
#include <math.h>

#define BB 2
#define LL 1024
#define DD 1024
#define NN 16
#define RR 64

// scratch (no device allocations allowed)
__device__ float g_tmp[BB * LL * RR];
__device__ float g_delta[BB * LL * DD];
__device__ float g_Bt[BB * LL * NN];
__device__ float g_Ct[BB * LL * NN];

// ---------------- fused projection: tmp, Bt, Ct in one pass over x ----------
// Every output keeps the exact k-ascending fmaf chain of the previous
// kernels => bit-identical tmp/Bt/Ct.
__global__ void __launch_bounds__(256) proj_fused(
    const float* __restrict__ A,   // x: [2048, 1024]
    const float* __restrict__ W1,  // W_dt1: [1024, 64]
    const float* __restrict__ WB,  // [1024, 16]
    const float* __restrict__ WC,  // [1024, 16]
    float* __restrict__ Tmp, float* __restrict__ Bt, float* __restrict__ Ct)
{
    __shared__ float As[16][64];
    __shared__ float W1s[64][64];
    __shared__ float WBs[64][16];
    __shared__ float WCs[64][16];

    int tid = threadIdx.x;
    int m0 = blockIdx.x * 16;

    // tmp role: thread -> (rows r0+4i, col nT)
    int r0 = tid >> 6;        // 0..3
    int nT = tid & 63;        // 0..63
    // btct role: thread -> (row rB, col nB)
    int rB = tid >> 4;        // 0..15
    int nB = tid & 15;        // 0..15

    float accT[4] = {0.f, 0.f, 0.f, 0.f};
    float accB = 0.f, accC = 0.f;

    for (int k0 = 0; k0 < 1024; k0 += 64) {
        __syncthreads();
        // stage x tile: 16 x 64
        for (int i = tid; i < 16 * 64; i += 256) {
            int rr = i >> 6, kk = i & 63;
            As[rr][kk] = A[(size_t)(m0 + rr) * 1024 + (k0 + kk)];
        }
        // stage W_dt1 chunk: 64 x 64
        for (int i = tid; i < 64 * 64; i += 256) {
            int kk = i >> 6, nn = i & 63;
            W1s[kk][nn] = W1[(size_t)(k0 + kk) * 64 + nn];
        }
        // stage WB/WC chunks: 64 x 16 each
        for (int i = tid; i < 64 * 16; i += 256) {
            int kk = i >> 4, nn = i & 15;
            WBs[kk][nn] = WB[(size_t)(k0 + kk) * 16 + nn];
            WCs[kk][nn] = WC[(size_t)(k0 + kk) * 16 + nn];
        }
        __syncthreads();

#pragma unroll
        for (int k = 0; k < 64; ++k) {
            float w = W1s[k][nT];
#pragma unroll
            for (int i = 0; i < 4; ++i)
                accT[i] = fmaf(As[r0 + 4 * i][k], w, accT[i]);
            float a = As[rB][k];
            accB = fmaf(a, WBs[k][nB], accB);
            accC = fmaf(a, WCs[k][nB], accC);
        }
    }

#pragma unroll
    for (int i = 0; i < 4; ++i)
        Tmp[(size_t)(m0 + r0 + 4 * i) * 64 + nT] = accT[i];
    Bt[(size_t)(m0 + rB) * 16 + nB] = accB;
    Ct[(size_t)(m0 + rB) * 16 + nB] = accC;
}

// ---------------- delta GEMM + softplus (unchanged numerics) ----------------
__global__ void __launch_bounds__(256) delta_gemm(
    const float* __restrict__ T, const float* __restrict__ W,
    float* __restrict__ C)
{
    __shared__ float ts[8][64];
    int tid = threadIdx.x;
    int m0 = blockIdx.y * 8;
    int n  = blockIdx.x * 256 + tid;

    for (int i = tid; i < 8 * 64; i += 256)
        ts[i / 64][i % 64] = T[(size_t)(m0 + i / 64) * 64 + (i % 64)];
    __syncthreads();

    float acc[8];
#pragma unroll
    for (int r = 0; r < 8; ++r) acc[r] = 0.f;

#pragma unroll
    for (int k = 0; k < 64; ++k) {
        float w = W[(size_t)k * 1024 + n];
#pragma unroll
        for (int r = 0; r < 8; ++r)
            acc[r] = fmaf(ts[r][k], w, acc[r]);
    }

#pragma unroll
    for (int r = 0; r < 8; ++r) {
        float v = acc[r];
        v = fmaxf(v, 0.f) + log1pf(expf(-fabsf(v)));
        C[(size_t)(m0 + r) * 1024 + n] = v;
    }
}

// ---------------- sequential resonance scan (op-for-op faithful) ----------------
// R3 geometry (1 chain/thread, 2 warps/SMSP — TLP-optimal). Changes vs R3 are
// scheduling-only (bit-exact): unroll-2 on the t-loop + max register budget so
// ptxas can overlap step t+1's h-independent prelude into step t's stalls.
__global__ void __launch_bounds__(256, 1) scan_k(
    const float* __restrict__ x, const float* __restrict__ A_log,
    const float* __restrict__ Dskip, float* __restrict__ y)
{
    int tid = threadIdx.x;
    int bid = blockIdx.x;                 // 0..127
    int b = bid >> 6;                     // 0..1
    int d = ((bid & 63) << 4) | (tid >> 4);
    int n = tid & 15;

    float An = expf(A_log[n]);
    float phi = (float)n * 0.39269908169872414f;
    float sphi, cphi;
    sincosf(phi, &sphi, &cphi);
    float hx = __fmul_rn(0.01f, cphi), hy = __fmul_rn(0.01f, sphi);
    float dsk = Dskip[d];

    size_t rowbase = ((size_t)b * LL) * DD + d;
    const float* xp = x + rowbase;
    const float* dp = g_delta + rowbase;
    const float* bp = g_Bt + ((size_t)b * LL) * NN + n;
    const float* cp = g_Ct + ((size_t)b * LL) * NN + n;
    float* yp = y + rowbase;

    float xv = __ldg(xp);
    float dv = __ldg(dp);
    float bn = __ldg(bp);
    float cn = __ldg(cp);

#pragma unroll 2
    for (int t = 0; t < LL; ++t) {
        int tn = (t < LL - 1) ? (t + 1) : t;
        float xv2 = __ldg(xp + (size_t)tn * DD);
        float dv2 = __ldg(dp + (size_t)tn * DD);
        float bn2 = __ldg(bp + tn * NN);
        float cn2 = __ldg(cp + tn * NN);

        // ---- fractal_compress(h, e) ----
        float mag = __fsqrt_rn(__fadd_rn(__fadd_rn(__fmul_rn(hx, hx), __fmul_rn(hy, hy)), 1e-8f));
        float ph  = atan2f(hy, __fadd_rn(hx, 1e-10f));
        float e   = __fadd_rn(1.0f, __fmul_rn(dv, An));
        float cm  = fminf(expf(__fmul_rn(e, logf(__fadd_rn(mag, 1e-8f)))), 10.0f);
        float sph, cph;
        sincosf(ph, &sph, &cph);
        float hcx = __fmul_rn(cm, cph);
        float hcy = __fmul_rn(cm, sph);

        // ---- injection on carrier phases ----
        float u   = __fmul_rn(xv, bn);
        float ijx = __fmul_rn(u, cphi);
        float ijy = __fmul_rn(u, sphi);

        // ---- resonance gate: gamma = 0.5 * cos((pa-pb)/2)^2 ----
        float pa = atan2f(ijy, __fadd_rn(ijx, 1e-10f));
        float pb = atan2f(hcy, __fadd_rn(hcx, 1e-10f));
        float cd = cosf(__fmul_rn(__fsub_rn(pa, pb), 0.5f));
        float gam = __fmul_rn(0.5f, __fmul_rn(cd, cd));

        // ---- inject + mag_squash ----
        float sx = __fadd_rn(hcx, __fmul_rn(gam, ijx));
        float sy = __fadd_rn(hcy, __fmul_rn(gam, ijy));
        float sm = __fsqrt_rn(__fadd_rn(__fadd_rn(__fmul_rn(sx, sx), __fmul_rn(sy, sy)), 1e-8f));
        float ps = atan2f(sy, __fadd_rn(sx, 1e-10f));
        float th = tanhf(sm);
        float sps, cps;
        sincosf(ps, &sps, &cps);
        hx = __fmul_rn(th, cps);
        hy = __fmul_rn(th, sps);

        // ---- readout ----
        float v = __fmul_rn(hx, cn);
        v += __shfl_xor_sync(0xffffffffu, v, 8);
        v += __shfl_xor_sync(0xffffffffu, v, 4);
        v += __shfl_xor_sync(0xffffffffu, v, 2);
        v += __shfl_xor_sync(0xffffffffu, v, 1);
        if (n == 0) yp[(size_t)t * DD] = __fadd_rn(__fmul_rn(xv, dsk), v);

        xv = xv2; dv = dv2; bn = bn2; cn = cn2;
    }
}

extern "C" void kernel_launch(void* const* d_in, const int* in_sizes, int n_in,
                              void* d_out, int out_size)
{
    const float *x = 0, *A_log = 0, *W_dt1 = 0, *W_dt2 = 0, *W_B = 0, *W_C = 0, *Dskip = 0;
    for (int i = 0; i < n_in; ++i) {
        const float* p = (const float*)d_in[i];
        int s = in_sizes[i];
        if (s == BB * LL * DD)      { if (!x) x = p; }
        else if (s == NN)           { if (!A_log) A_log = p; }
        else if (s == DD * RR)      { if (!W_dt1) W_dt1 = p; else W_dt2 = p; }
        else if (s == DD * NN)      { if (!W_B) W_B = p; else W_C = p; }
        else if (s == DD)           { if (!Dskip) Dskip = p; }
    }
    float* y = (float*)d_out;

    float *tmp, *delta, *bt, *ct;
    cudaGetSymbolAddress((void**)&tmp,   g_tmp);
    cudaGetSymbolAddress((void**)&delta, g_delta);
    cudaGetSymbolAddress((void**)&bt,    g_Bt);
    cudaGetSymbolAddress((void**)&ct,    g_Ct);

    const int M = BB * LL;  // 2048
    // tmp, Bt, Ct in one fused pass over x (bit-identical chains)
    proj_fused<<<M / 16, 256>>>(x, W_dt1, W_B, W_C, tmp, bt, ct);
    // delta = softplus(tmp @ W_dt2)
    delta_gemm<<<dim3(4, M / 8), 256>>>(tmp, W_dt2, delta);
    // sequential scan (R3 geometry, scheduling-improved)
    scan_k<<<128, 256>>>(x, A_log, Dskip, y);
}